// round 12
// baseline (speedup 1.0000x reference)
#include <cuda_runtime.h>

#define VOCABN 1000
#define EMBN   128
#define HIDN   256
#define G4N    1024   // 4*HID
#define BN     64
#define TN     1024

#define CL     8      // CTAs per cluster
#define GB     4      // batch rows per cluster
#define NTH    512    // 16 warps x 32 lanes

// Precomputed per-vocab gate projections: proj[v][g] = emb[v].W_ih[g] + b_ih[g] + b_hh[g]
__device__ float g_proj[VOCABN * G4N];

// ---------------- packed f32x2 helpers ----------------
__device__ __forceinline__ unsigned long long fma2(unsigned long long a,
                                                   unsigned long long b,
                                                   unsigned long long c) {
    unsigned long long d;
    asm("fma.rn.f32x2 %0, %1, %2, %3;" : "=l"(d) : "l"(a), "l"(b), "l"(c));
    return d;
}
__device__ __forceinline__ float lo32(unsigned long long v) {
    return __uint_as_float((unsigned)v);
}
__device__ __forceinline__ float hi32(unsigned long long v) {
    return __uint_as_float((unsigned)(v >> 32));
}

__device__ __forceinline__ float sigf(float x) {
    return __fdividef(1.0f, 1.0f + __expf(-x));
}
__device__ __forceinline__ float tanhf_(float x) {
    return 1.0f - __fdividef(2.0f, __expf(2.0f * x) + 1.0f);
}

// ---------------- cluster smem / mbarrier helpers ----------------
__device__ __forceinline__ unsigned smem_u32(const void* p) {
    return (unsigned)__cvta_generic_to_shared(p);
}
__device__ __forceinline__ void mbar_init(unsigned a, unsigned cnt) {
    asm volatile("mbarrier.init.shared.b64 [%0], %1;" :: "r"(a), "r"(cnt) : "memory");
}
__device__ __forceinline__ unsigned mapa_u32(unsigned a, unsigned rank) {
    unsigned r;
    asm("mapa.shared::cluster.u32 %0, %1, %2;" : "=r"(r) : "r"(a), "r"(rank));
    return r;
}
__device__ __forceinline__ void mbar_arm(unsigned a, unsigned tx_bytes) {
    asm volatile("mbarrier.arrive.expect_tx.shared.b64 _, [%0], %1;"
                 :: "r"(a), "r"(tx_bytes) : "memory");
}
// remote store, counts bytes into the destination CTA's mbarrier
__device__ __forceinline__ void st_async_f32(unsigned dst, float v, unsigned mb) {
    asm volatile(
        "st.async.shared::cluster.mbarrier::complete_tx::bytes.b32 [%0], %1, [%2];"
        :: "r"(dst), "r"(__float_as_uint(v)), "r"(mb) : "memory");
}
__device__ __forceinline__ void mbar_wait(unsigned a, unsigned parity) {
    asm volatile(
        "{\n\t"
        ".reg .pred P;\n\t"
        "mbarrier.try_wait.parity.acquire.cluster.shared::cta.b64 P, [%0], %1;\n\t"
        "@P bra.uni WDONE_%=;\n\t"
        "WLOOP_%=:\n\t"
        "mbarrier.try_wait.parity.acquire.cluster.shared::cta.b64 P, [%0], %1, 0x989680;\n\t"
        "@!P bra.uni WLOOP_%=;\n\t"
        "WDONE_%=:\n\t"
        "}"
        :: "r"(a), "r"(parity) : "memory");
}
__device__ __forceinline__ void cluster_sync_once() {
    asm volatile("barrier.cluster.arrive.aligned;" ::: "memory");
    asm volatile("barrier.cluster.wait.aligned;" ::: "memory");
}

// ---------------------------------------------------------------------------
// Kernel 1: vocab projection table. 125 blocks x 256 threads, 8 vocab/block.
// ---------------------------------------------------------------------------
__global__ void __launch_bounds__(256) proj_kernel(
    const float* __restrict__ emb, const float* __restrict__ W_ih,
    const float* __restrict__ b_ih, const float* __restrict__ b_hh)
{
    __shared__ float4 es4[8][EMBN / 4];
    const int v0 = blockIdx.x * 8;
    const int tid = threadIdx.x;
    for (int i = tid; i < 8 * EMBN; i += 256) {
        int v = i >> 7, e = i & 127;
        ((float*)es4)[v * EMBN + e] = emb[(v0 + v) * EMBN + e];
    }
    __syncthreads();

    const float4* W4 = (const float4*)W_ih;
#pragma unroll
    for (int rr = 0; rr < 4; rr++) {
        int g = tid + rr * 256;
        float acc[8];
#pragma unroll
        for (int v = 0; v < 8; v++) acc[v] = 0.f;
        for (int e4 = 0; e4 < EMBN / 4; e4++) {
            float4 w = W4[g * (EMBN / 4) + e4];
#pragma unroll
            for (int v = 0; v < 8; v++) {
                float4 x = es4[v][e4];
                acc[v] += w.x * x.x + w.y * x.y + w.z * x.z + w.w * x.w;
            }
        }
        float bias = b_ih[g] + b_hh[g];
#pragma unroll
        for (int v = 0; v < 8; v++)
            g_proj[(v0 + v) * G4N + g] = acc[v] + bias;
    }
}

// ---------------------------------------------------------------------------
// Kernel 2: recurrence, BARRIER-FREE inner loop. 16 clusters x 8 CTAs;
// cluster owns 4 batch rows. Warp w owns h-indices {base+2w, base+2w+1}.
// Lane = (gate g = bits[4:3], h-pair p = bit 2, k-quarter q = bits[1:0]).
// Per step per warp: mbar wait -> matvec (W in regs, h broadcast LDS) ->
// shfl k-reduce over q -> +xproj -> 2-round shfl 4x4 transpose (gates ->
// batches) -> per-lane cell -> st.async push. NO __syncthreads, NO psum
// SMEM roundtrip; warps are coupled only through the tx-mbarrier.
// ---------------------------------------------------------------------------
__global__ void __launch_bounds__(NTH, 1) __cluster_dims__(CL, 1, 1)
lstm_kernel(const int* __restrict__ tokens, const int* __restrict__ lengths,
            const float* __restrict__ W_hh, float* __restrict__ out)
{
    // [buf][quarter][batch][68]: 68-float batch stride -> 16B-aligned float4,
    // q-blocks 1088B apart (2-way LDS conflict = rt floor, effectively free).
    __shared__ float hb[2][4][GB][68];
    __shared__ __align__(8) unsigned long long mbar[2];

    const int rank = blockIdx.x;               // 0..7
    const int cid  = blockIdx.y;               // 0..15
    const int tid  = threadIdx.x;
    const int w    = tid >> 5;                 // warp 0..15
    const int lane = tid & 31;
    const int q    = lane & 3;                 // k-quarter
    const int p    = (lane >> 2) & 1;          // h-pair
    const int gf   = (lane >> 3) & 3;          // gate (pre-transpose) / batch (post)
    const int base = rank * 32;
    const int hloc = 2 * w + p;                // my h index within CTA's 32
    const int b0   = cid * GB;
    const int grow = gf * HIDN + base + hloc;  // my W_hh row
    const unsigned TXB = 4096;                 // 8 ranks x 32 h x 4 batches x 4B

    // W slice into registers: 64 floats (k-quarter of my gate row) = 32 pairs
    unsigned long long wpair[32];
    {
        const ulonglong2* wr =
            (const ulonglong2*)(W_hh + (size_t)grow * HIDN + q * 64);
#pragma unroll
        for (int j = 0; j < 16; j++) {
            ulonglong2 v = wr[j];
            wpair[2 * j]     = v.x;
            wpair[2 * j + 1] = v.y;
        }
    }

    const unsigned mb0 = smem_u32(&mbar[0]);
    const unsigned mb1 = smem_u32(&mbar[1]);
    if (tid == 0) {
        mbar_init(mb0, 1);
        mbar_init(mb1, 1);
        mbar_arm(mb1, TXB);    // pre-arm for t=1 data (arrives into hb[1])
    }
    for (int i = tid; i < 2 * 4 * GB * 68; i += NTH) ((float*)hb)[i] = 0.f;
    __syncthreads();
    cluster_sync_once();       // init + hb zeros visible cluster-wide

    const bool active = (q == 0);              // cell/push lanes (8 per warp)
    const int  mylen  = active ? lengths[b0 + gf] : 0;  // post-transpose batch = gf

    const int len0 = lengths[b0 + 0];
    const int len1 = lengths[b0 + 1];
    const int len2 = lengths[b0 + 2];
    const int len3 = lengths[b0 + 3];
    int steps = max(max(len0, len1), max(len2, len3));
    if (steps > TN) steps = TN;

    // input projections: active lanes hold xw[gate row grow][4 batches]
    float xw0 = 0.f, xw1 = 0.f, xw2 = 0.f, xw3 = 0.f;
    if (active) {
        xw0 = g_proj[tokens[(b0 + 0) * TN] * G4N + grow];
        xw1 = g_proj[tokens[(b0 + 1) * TN] * G4N + grow];
        xw2 = g_proj[tokens[(b0 + 2) * TN] * G4N + grow];
        xw3 = g_proj[tokens[(b0 + 3) * TN] * G4N + grow];
    }

    float creg = 0.f, hreg = 0.f;
    unsigned ph0 = 0, ph1 = 0;
    const int r0 = (lane >> 3) & 1;            // transpose round selectors
    const int r1 = (lane >> 4) & 1;

    for (int t = 0; t < steps; t++) {
        const int buf = t & 1;
        // wait for h(t) (skip t=0: hb[0] prezeroed); re-arm for t+2.
        // Safety: arrivals for t+2 need global wait(t+1), which needs warp0's
        // push(t+1), which follows this arm. No __syncthreads required.
        if (t) {
            if (buf) { mbar_wait(mb1, ph1); ph1 ^= 1; }
            else     { mbar_wait(mb0, ph0); ph0 ^= 1; }
        }
        if (tid == 0) mbar_arm(buf ? mb1 : mb0, TXB);

        // prefetch next step's input projection (L2 latency hidden by matvec)
        float xn0 = 0.f, xn1 = 0.f, xn2 = 0.f, xn3 = 0.f;
        if (active) {
            int tn = min(t + 1, TN - 1);
            xn0 = g_proj[tokens[(b0 + 0) * TN + tn] * G4N + grow];
            xn1 = g_proj[tokens[(b0 + 1) * TN + tn] * G4N + grow];
            xn2 = g_proj[tokens[(b0 + 2) * TN + tn] * G4N + grow];
            xn3 = g_proj[tokens[(b0 + 3) * TN + tn] * G4N + grow];
        }

        // packed matvec: my gate row, my k-quarter, 4 batches
        const float* hq = &hb[buf][q][0][0];
        unsigned long long a0 = 0ull, a1 = 0ull, a2 = 0ull, a3 = 0ull;
#pragma unroll
        for (int c = 0; c < 16; c++) {
            ulonglong2 h0 = *(const ulonglong2*)(hq +   0 + 4 * c);
            ulonglong2 h1 = *(const ulonglong2*)(hq +  68 + 4 * c);
            ulonglong2 h2 = *(const ulonglong2*)(hq + 136 + 4 * c);
            ulonglong2 h3 = *(const ulonglong2*)(hq + 204 + 4 * c);
            a0 = fma2(wpair[2 * c],     h0.x, a0);
            a1 = fma2(wpair[2 * c],     h1.x, a1);
            a2 = fma2(wpair[2 * c],     h2.x, a2);
            a3 = fma2(wpair[2 * c],     h3.x, a3);
            a0 = fma2(wpair[2 * c + 1], h0.y, a0);
            a1 = fma2(wpair[2 * c + 1], h1.y, a1);
            a2 = fma2(wpair[2 * c + 1], h2.y, a2);
            a3 = fma2(wpair[2 * c + 1], h3.y, a3);
        }
        // k-reduce across the 4 q-lanes (bits 0..1) + fold in input projection
        float v0 = lo32(a0) + hi32(a0);
        float v1 = lo32(a1) + hi32(a1);
        float v2 = lo32(a2) + hi32(a2);
        float v3 = lo32(a3) + hi32(a3);
        v0 += __shfl_xor_sync(0xffffffffu, v0, 1);
        v1 += __shfl_xor_sync(0xffffffffu, v1, 1);
        v2 += __shfl_xor_sync(0xffffffffu, v2, 1);
        v3 += __shfl_xor_sync(0xffffffffu, v3, 1);
        v0 += __shfl_xor_sync(0xffffffffu, v0, 2);
        v1 += __shfl_xor_sync(0xffffffffu, v1, 2);
        v2 += __shfl_xor_sync(0xffffffffu, v2, 2);
        v3 += __shfl_xor_sync(0xffffffffu, v3, 2);
        v0 += xw0; v1 += xw1; v2 += xw2; v3 += xw3;   // garbage on q!=0: inert
        xw0 = xn0; xw1 = xn1; xw2 = xn2; xw3 = xn3;

        // 4x4 transpose (gates <-> batches) across lanes xor 8 / xor 16.
        // After: lane with g-field == b holds v0..v3 = gates i,f,g,o of batch b.
        {
            float sA = r0 ? v0 : v1;
            float sB = r0 ? v2 : v3;
            sA = __shfl_xor_sync(0xffffffffu, sA, 8);
            sB = __shfl_xor_sync(0xffffffffu, sB, 8);
            if (r0) { v0 = sA; v2 = sB; } else { v1 = sA; v3 = sB; }
        }
        {
            float tA = r1 ? v0 : v2;
            float tB = r1 ? v1 : v3;
            tA = __shfl_xor_sync(0xffffffffu, tA, 16);
            tB = __shfl_xor_sync(0xffffffffu, tB, 16);
            if (r1) { v0 = tA; v1 = tB; } else { v2 = tA; v3 = tB; }
        }

        // cell + push, fully warp-local
        if (active) {
            float i_ = sigf(v0), f_ = sigf(v1), g_ = tanhf_(v2), o_ = sigf(v3);
            float cn = f_ * creg + i_ * g_;
            float hn = o_ * tanhf_(cn);
            if (t < mylen) { creg = cn; hreg = hn; }

            if (t + 1 < steps) {
                const int nb = buf ^ 1;
                // my h value lands at quarter rank>>1, slot (rank&1)*32 + hloc
                const unsigned dloc =
                    smem_u32(&hb[nb][rank >> 1][gf][(rank & 1) * 32 + hloc]);
                const unsigned mloc = nb ? mb1 : mb0;
#pragma unroll
                for (int r = 0; r < CL; r++)
                    st_async_f32(mapa_u32(dloc, r), hreg, mapa_u32(mloc, r));
            }
        }
    }

    if (active)
        out[(b0 + gf) * HIDN + base + hloc] = hreg;
}

// ---------------------------------------------------------------------------
extern "C" void kernel_launch(void* const* d_in, const int* in_sizes, int n_in,
                              void* d_out, int out_size)
{
    const int*   tokens  = (const int*)d_in[0];
    const int*   lengths = (const int*)d_in[1];
    const float* emb     = (const float*)d_in[2];
    const float* W_ih    = (const float*)d_in[3];
    const float* W_hh    = (const float*)d_in[4];
    const float* b_ih    = (const float*)d_in[5];
    const float* b_hh    = (const float*)d_in[6];
    float* out = (float*)d_out;

    proj_kernel<<<VOCABN / 8, 256>>>(emb, W_ih, b_ih, b_hh);

    dim3 grid(CL, BN / GB);
    lstm_kernel<<<grid, NTH>>>(tokens, lengths, W_hh, out);
}

// round 13
// speedup vs baseline: 2.7764x; 2.7764x over previous
#include <cuda_runtime.h>

#define VOCABN 1000
#define EMBN   128
#define HIDN   256
#define G4N    1024   // 4*HID
#define BN     64
#define TN     1024

#define CL     8      // CTAs per cluster
#define NTH    512    // 128 gate rows x 4 k-quarters

// Precomputed per-vocab gate projections: proj[v][g] = emb[v].W_ih[g] + b_ih[g] + b_hh[g]
__device__ float g_proj[VOCABN * G4N];

// ---------------- packed f32x2 helpers ----------------
__device__ __forceinline__ unsigned long long fma2(unsigned long long a,
                                                   unsigned long long b,
                                                   unsigned long long c) {
    unsigned long long d;
    asm("fma.rn.f32x2 %0, %1, %2, %3;" : "=l"(d) : "l"(a), "l"(b), "l"(c));
    return d;
}
__device__ __forceinline__ float lo32(unsigned long long v) {
    return __uint_as_float((unsigned)v);
}
__device__ __forceinline__ float hi32(unsigned long long v) {
    return __uint_as_float((unsigned)(v >> 32));
}

__device__ __forceinline__ float sigf(float x) {
    return __fdividef(1.0f, 1.0f + __expf(-x));
}
__device__ __forceinline__ float tanhf_(float x) {
    return 1.0f - __fdividef(2.0f, __expf(2.0f * x) + 1.0f);
}

// ---------------- cluster smem / mbarrier helpers ----------------
__device__ __forceinline__ unsigned smem_u32(const void* p) {
    return (unsigned)__cvta_generic_to_shared(p);
}
__device__ __forceinline__ void mbar_init(unsigned a, unsigned cnt) {
    asm volatile("mbarrier.init.shared.b64 [%0], %1;" :: "r"(a), "r"(cnt) : "memory");
}
__device__ __forceinline__ unsigned mapa_u32(unsigned a, unsigned rank) {
    unsigned r;
    asm("mapa.shared::cluster.u32 %0, %1, %2;" : "=r"(r) : "r"(a), "r"(rank));
    return r;
}
__device__ __forceinline__ void mbar_arm(unsigned a, unsigned tx_bytes) {
    asm volatile("mbarrier.arrive.expect_tx.shared.b64 _, [%0], %1;"
                 :: "r"(a), "r"(tx_bytes) : "memory");
}
__device__ __forceinline__ void mbar_arrive(unsigned a) {
    asm volatile("mbarrier.arrive.shared.b64 _, [%0];" :: "r"(a) : "memory");
}
// remote store, counts bytes into the destination CTA's mbarrier
__device__ __forceinline__ void st_async_f32(unsigned dst, float v, unsigned mb) {
    asm volatile(
        "st.async.shared::cluster.mbarrier::complete_tx::bytes.b32 [%0], %1, [%2];"
        :: "r"(dst), "r"(__float_as_uint(v)), "r"(mb) : "memory");
}
__device__ __forceinline__ void mbar_wait(unsigned a, unsigned parity) {
    asm volatile(
        "{\n\t"
        ".reg .pred P;\n\t"
        "mbarrier.try_wait.parity.acquire.cluster.shared::cta.b64 P, [%0], %1;\n\t"
        "@P bra.uni WDONE_%=;\n\t"
        "WLOOP_%=:\n\t"
        "mbarrier.try_wait.parity.acquire.cluster.shared::cta.b64 P, [%0], %1, 0x989680;\n\t"
        "@!P bra.uni WLOOP_%=;\n\t"
        "WDONE_%=:\n\t"
        "}"
        :: "r"(a), "r"(parity) : "memory");
}
__device__ __forceinline__ void mbar_wait_cta(unsigned a, unsigned parity) {
    asm volatile(
        "{\n\t"
        ".reg .pred P;\n\t"
        "mbarrier.try_wait.parity.acquire.cta.shared::cta.b64 P, [%0], %1;\n\t"
        "@P bra.uni WDONE_%=;\n\t"
        "WLOOP_%=:\n\t"
        "mbarrier.try_wait.parity.acquire.cta.shared::cta.b64 P, [%0], %1, 0x989680;\n\t"
        "@!P bra.uni WLOOP_%=;\n\t"
        "WDONE_%=:\n\t"
        "}"
        :: "r"(a), "r"(parity) : "memory");
}
__device__ __forceinline__ void cluster_sync_once() {
    asm volatile("barrier.cluster.arrive.aligned;" ::: "memory");
    asm volatile("barrier.cluster.wait.aligned;" ::: "memory");
}

// ---------------------------------------------------------------------------
// Kernel 1: vocab projection table. 125 blocks x 256 threads, 8 vocab/block.
// ---------------------------------------------------------------------------
__global__ void __launch_bounds__(256) proj_kernel(
    const float* __restrict__ emb, const float* __restrict__ W_ih,
    const float* __restrict__ b_ih, const float* __restrict__ b_hh)
{
    __shared__ float4 es4[8][EMBN / 4];
    const int v0 = blockIdx.x * 8;
    const int tid = threadIdx.x;
    for (int i = tid; i < 8 * EMBN; i += 256) {
        int v = i >> 7, e = i & 127;
        ((float*)es4)[v * EMBN + e] = emb[(v0 + v) * EMBN + e];
    }
    __syncthreads();

    const float4* W4 = (const float4*)W_ih;
#pragma unroll
    for (int rr = 0; rr < 4; rr++) {
        int g = tid + rr * 256;
        float acc[8];
#pragma unroll
        for (int v = 0; v < 8; v++) acc[v] = 0.f;
        for (int e4 = 0; e4 < EMBN / 4; e4++) {
            float4 w = W4[g * (EMBN / 4) + e4];
#pragma unroll
            for (int v = 0; v < 8; v++) {
                float4 x = es4[v][e4];
                acc[v] += w.x * x.x + w.y * x.y + w.z * x.z + w.w * x.w;
            }
        }
        float bias = b_ih[g] + b_hh[g];
#pragma unroll
        for (int v = 0; v < 8; v++)
            g_proj[(v0 + v) * G4N + g] = acc[v] + bias;
    }
}

// ---------------------------------------------------------------------------
// Kernel 2: recurrence. 16 clusters x 8 CTAs; cluster owns 4 batches as TWO
// independent groups of 2, time-interleaved. Thread = (gate row lr, quarter q;
// q warp-uniform). W_hh k-quarter of one gate row in registers (32 u64).
// Per group-step: h-mbar wait -> matvec -> psum STS -> mbarrier.arrive
// (NON-BLOCKING; producers stream into the other group's matvec) ->
// crew-g (q==g, 128 threads) try_waits the psum barrier, does the cell,
// st.async-pushes h_new. The cell tail overlaps the other group's matvec.
// ---------------------------------------------------------------------------
__global__ void __launch_bounds__(NTH, 1) __cluster_dims__(CL, 1, 1)
lstm_kernel(const int* __restrict__ tokens, const int* __restrict__ lengths,
            const float* __restrict__ W_hh, float* __restrict__ out)
{
    __shared__ float hb[2][2][2][HIDN];        // 8 KB: [group][buf][batch][k]
    __shared__ float psum[2][2][4][2][128];    // 16 KB: [g][buf][q][batch][row]
    __shared__ __align__(8) unsigned long long mbh[2][2];  // h exchange
    __shared__ __align__(8) unsigned long long pmb[2][2];  // psum count-512

    const int rank = blockIdx.x;               // 0..7
    const int cid  = blockIdx.y;               // 0..15
    const int tid  = threadIdx.x;
    const int lr   = tid & 127;                // gate row 0..127
    const int q    = tid >> 7;                 // k-quarter 0..3 (warp-uniform)
    const int base = rank * 32;
    const int b0   = cid * 4;
    const unsigned TXB = CL * 32 * 2 * 4;      // 2048 B per group exchange phase
    const int grow = (lr >> 5) * HIDN + base + (lr & 31);  // my W_hh row

    // --- W slice into registers: 64 floats (k-quarter of a row) = 32 pairs ---
    unsigned long long wpair[32];
    {
        const ulonglong2* wr =
            (const ulonglong2*)(W_hh + (size_t)grow * HIDN + q * 64);
#pragma unroll
        for (int j = 0; j < 16; j++) {
            ulonglong2 v = wr[j];
            wpair[2 * j]     = v.x;
            wpair[2 * j + 1] = v.y;
        }
    }

    if (tid == 0) {
#pragma unroll
        for (int g = 0; g < 2; g++) {
            mbar_init(smem_u32(&mbh[g][0]), 1);
            mbar_init(smem_u32(&mbh[g][1]), 1);
            mbar_arm(smem_u32(&mbh[g][1]), TXB);   // pre-arm t=1
            mbar_init(smem_u32(&pmb[g][0]), NTH);
            mbar_init(smem_u32(&pmb[g][1]), NTH);
        }
    }
    for (int i = tid; i < 2 * 2 * 2 * HIDN; i += NTH) ((float*)hb)[i] = 0.f;
    __syncthreads();
    cluster_sync_once();       // init + hb zeros visible cluster-wide

    // crew identity: quarter q is the cell crew for group q (q<2)
    const int pr = lr >> 1;         // 0..63
    const int s  = lr & 1;          // 0 -> {i,f}, 1 -> {g,o}
    const int hl = pr & 31;
    const int bb = pr >> 5;         // batch within group
    const int mylen = (q < 2) ? lengths[b0 + 2 * q + bb] : 0;

    const int len0 = lengths[b0 + 0];
    const int len1 = lengths[b0 + 1];
    const int len2 = lengths[b0 + 2];
    const int len3 = lengths[b0 + 3];
    int sg[2];
    sg[0] = min(max(len0, len1), TN);
    sg[1] = min(max(len2, len3), TN);
    const int steps = max(sg[0], sg[1]);

    // input projections: q==0 threads hold xw for BOTH groups
    float xw[2][2];
    if (q == 0) {
#pragma unroll
        for (int g = 0; g < 2; g++) {
            xw[g][0] = g_proj[tokens[(b0 + 2 * g + 0) * TN] * G4N + grow];
            xw[g][1] = g_proj[tokens[(b0 + 2 * g + 1) * TN] * G4N + grow];
        }
    }

    float creg = 0.f, hreg = 0.f;             // crew cell state (its group)
    unsigned phh[2][2] = {{0u, 0u}, {0u, 0u}}; // h-mbar parities
    unsigned pq0 = 0, pq1 = 0;                 // crew psum-mbar parities

    for (int t = 0; t < steps; t++) {
        const int buf = t & 1;
        const int nb  = buf ^ 1;
#pragma unroll
        for (int g = 0; g < 2; g++) {
            if (t >= sg[g]) continue;          // group done (uniform across cluster)

            // wait for this group's h(t) (skip t=0: prezeroed); re-arm for t+2
            if (t) {
                if (buf) { mbar_wait(smem_u32(&mbh[g][1]), phh[g][1]); phh[g][1] ^= 1u; }
                else     { mbar_wait(smem_u32(&mbh[g][0]), phh[g][0]); phh[g][0] ^= 1u; }
            }
            if (tid == 0) mbar_arm(smem_u32(&mbh[g][buf]), TXB);

            // prefetch next input projection
            float xn0, xn1;
            if (q == 0) {
                int tn = min(t + 1, TN - 1);
                xn0 = g_proj[tokens[(b0 + 2 * g + 0) * TN + tn] * G4N + grow];
                xn1 = g_proj[tokens[(b0 + 2 * g + 1) * TN + tn] * G4N + grow];
            }

            // packed matvec: my gate row, my k-quarter, this group's 2 batches
            const float* h0p = hb[g][buf][0] + q * 64;
            const float* h1p = hb[g][buf][1] + q * 64;
            unsigned long long a0 = 0ull, a1 = 0ull;
#pragma unroll
            for (int c = 0; c < 16; c++) {
                ulonglong2 h0 = *(const ulonglong2*)(h0p + c * 4);
                ulonglong2 h1 = *(const ulonglong2*)(h1p + c * 4);
                a0 = fma2(wpair[2 * c],     h0.x, a0);
                a1 = fma2(wpair[2 * c],     h1.x, a1);
                a0 = fma2(wpair[2 * c + 1], h0.y, a0);
                a1 = fma2(wpair[2 * c + 1], h1.y, a1);
            }
            if (q == 0) {
                psum[g][buf][0][0][lr] = lo32(a0) + hi32(a0) + xw[g][0];
                psum[g][buf][0][1][lr] = lo32(a1) + hi32(a1) + xw[g][1];
                xw[g][0] = xn0; xw[g][1] = xn1;
            } else {
                psum[g][buf][q][0][lr] = lo32(a0) + hi32(a0);
                psum[g][buf][q][1][lr] = lo32(a1) + hi32(a1);
            }
            // non-blocking psum-ready signal; producers stream onward
            mbar_arrive(smem_u32(&pmb[g][buf]));

            // crew for group g: wait psum, cell, push
            if (q == g) {
                if (buf) { mbar_wait_cta(smem_u32(&pmb[g][1]), pq1); pq1 ^= 1u; }
                else     { mbar_wait_cta(smem_u32(&pmb[g][0]), pq0); pq0 ^= 1u; }

                const int r0 = (s ? 64 : 0) + hl;
                const int r1 = (s ? 96 : 32) + hl;
                float gA = (psum[g][buf][0][bb][r0] + psum[g][buf][1][bb][r0]) +
                           (psum[g][buf][2][bb][r0] + psum[g][buf][3][bb][r0]);
                float gB = (psum[g][buf][0][bb][r1] + psum[g][buf][1][bb][r1]) +
                           (psum[g][buf][2][bb][r1] + psum[g][buf][3][bb][r1]);
                float u = s ? tanhf_(gA) : sigf(gA);
                float v = sigf(gB);
                float ou = __shfl_xor_sync(0xffffffffu, u, 1);
                float ov = __shfl_xor_sync(0xffffffffu, v, 1);
                float i_ = s ? ou : u;
                float f_ = s ? ov : v;
                float g_ = s ? u  : ou;
                float o_ = s ? v  : ov;
                float cn = f_ * creg + i_ * g_;
                float hn = o_ * tanhf_(cn);
                if (t < mylen) { creg = cn; hreg = hn; }

                if (t + 1 < sg[g]) {
                    const unsigned dloc = smem_u32(&hb[g][nb][bb][base + hl]);
                    const unsigned mloc = smem_u32(&mbh[g][nb]);
#pragma unroll
                    for (int r = 0; r < 4; r++) {
                        const unsigned rk = 4 * s + r;
                        st_async_f32(mapa_u32(dloc, rk), hreg, mapa_u32(mloc, rk));
                    }
                }
            }
        }
    }

    if (q < 2 && s == 0)
        out[(b0 + 2 * q + bb) * HIDN + base + hl] = hreg;
}

// ---------------------------------------------------------------------------
extern "C" void kernel_launch(void* const* d_in, const int* in_sizes, int n_in,
                              void* d_out, int out_size)
{
    const int*   tokens  = (const int*)d_in[0];
    const int*   lengths = (const int*)d_in[1];
    const float* emb     = (const float*)d_in[2];
    const float* W_ih    = (const float*)d_in[3];
    const float* W_hh    = (const float*)d_in[4];
    const float* b_ih    = (const float*)d_in[5];
    const float* b_hh    = (const float*)d_in[6];
    float* out = (float*)d_out;

    proj_kernel<<<VOCABN / 8, 256>>>(emb, W_ih, b_ih, b_hh);

    dim3 grid(CL, BN / 4);
    lstm_kernel<<<grid, NTH>>>(tokens, lengths, W_hh, out);
}

// round 14
// speedup vs baseline: 3.0150x; 1.0859x over previous
#include <cuda_runtime.h>

#define VOCABN 1000
#define EMBN   128
#define HIDN   256
#define G4N    1024   // 4*HID
#define BN     64
#define TN     1024

#define CL     8      // CTAs per cluster
#define GB     4      // batch rows per cluster
#define NTH    512    // 128 gate rows x 4 k-quarters

// Precomputed per-vocab gate projections: proj[v][g] = emb[v].W_ih[g] + b_ih[g] + b_hh[g]
__device__ float g_proj[VOCABN * G4N];

// ---------------- packed f32x2 helpers ----------------
__device__ __forceinline__ unsigned long long fma2(unsigned long long a,
                                                   unsigned long long b,
                                                   unsigned long long c) {
    unsigned long long d;
    asm("fma.rn.f32x2 %0, %1, %2, %3;" : "=l"(d) : "l"(a), "l"(b), "l"(c));
    return d;
}
__device__ __forceinline__ float lo32(unsigned long long v) {
    return __uint_as_float((unsigned)v);
}
__device__ __forceinline__ float hi32(unsigned long long v) {
    return __uint_as_float((unsigned)(v >> 32));
}

__device__ __forceinline__ float sigf(float x) {
    return __fdividef(1.0f, 1.0f + __expf(-x));
}
__device__ __forceinline__ float tanhf_(float x) {
    return 1.0f - __fdividef(2.0f, __expf(2.0f * x) + 1.0f);
}

// ---------------- cluster smem / mbarrier helpers ----------------
__device__ __forceinline__ unsigned smem_u32(const void* p) {
    return (unsigned)__cvta_generic_to_shared(p);
}
__device__ __forceinline__ void mbar_init(unsigned a, unsigned cnt) {
    asm volatile("mbarrier.init.shared.b64 [%0], %1;" :: "r"(a), "r"(cnt) : "memory");
}
__device__ __forceinline__ unsigned mapa_u32(unsigned a, unsigned rank) {
    unsigned r;
    asm("mapa.shared::cluster.u32 %0, %1, %2;" : "=r"(r) : "r"(a), "r"(rank));
    return r;
}
__device__ __forceinline__ void mbar_arm(unsigned a, unsigned tx_bytes) {
    asm volatile("mbarrier.arrive.expect_tx.shared.b64 _, [%0], %1;"
                 :: "r"(a), "r"(tx_bytes) : "memory");
}
// remote vector store (16 B), counts bytes into the destination's mbarrier
__device__ __forceinline__ void st_async_f32x4(unsigned dst, float v0, float v1,
                                               float v2, float v3, unsigned mb) {
    asm volatile(
        "st.async.shared::cluster.mbarrier::complete_tx::bytes.v4.b32 "
        "[%0], {%1, %2, %3, %4}, [%5];"
        :: "r"(dst), "r"(__float_as_uint(v0)), "r"(__float_as_uint(v1)),
           "r"(__float_as_uint(v2)), "r"(__float_as_uint(v3)), "r"(mb)
        : "memory");
}
__device__ __forceinline__ void mbar_wait(unsigned a, unsigned parity) {
    asm volatile(
        "{\n\t"
        ".reg .pred P;\n\t"
        "mbarrier.try_wait.parity.acquire.cluster.shared::cta.b64 P, [%0], %1;\n\t"
        "@P bra.uni WDONE_%=;\n\t"
        "WLOOP_%=:\n\t"
        "mbarrier.try_wait.parity.acquire.cluster.shared::cta.b64 P, [%0], %1, 0x989680;\n\t"
        "@!P bra.uni WLOOP_%=;\n\t"
        "WDONE_%=:\n\t"
        "}"
        :: "r"(a), "r"(parity) : "memory");
}
__device__ __forceinline__ void cluster_sync_once() {
    asm volatile("barrier.cluster.arrive.aligned;" ::: "memory");
    asm volatile("barrier.cluster.wait.aligned;" ::: "memory");
}

// ---------------------------------------------------------------------------
// Kernel 1: vocab projection table. 125 blocks x 256 threads, 8 vocab/block.
// ---------------------------------------------------------------------------
__global__ void __launch_bounds__(256) proj_kernel(
    const float* __restrict__ emb, const float* __restrict__ W_ih,
    const float* __restrict__ b_ih, const float* __restrict__ b_hh)
{
    __shared__ float4 es4[8][EMBN / 4];
    const int v0 = blockIdx.x * 8;
    const int tid = threadIdx.x;
    for (int i = tid; i < 8 * EMBN; i += 256) {
        int v = i >> 7, e = i & 127;
        ((float*)es4)[v * EMBN + e] = emb[(v0 + v) * EMBN + e];
    }
    __syncthreads();

    const float4* W4 = (const float4*)W_ih;
#pragma unroll
    for (int rr = 0; rr < 4; rr++) {
        int g = tid + rr * 256;
        float acc[8];
#pragma unroll
        for (int v = 0; v < 8; v++) acc[v] = 0.f;
        for (int e4 = 0; e4 < EMBN / 4; e4++) {
            float4 w = W4[g * (EMBN / 4) + e4];
#pragma unroll
            for (int v = 0; v < 8; v++) {
                float4 x = es4[v][e4];
                acc[v] += w.x * x.x + w.y * x.y + w.z * x.z + w.w * x.w;
            }
        }
        float bias = b_ih[g] + b_hh[g];
#pragma unroll
        for (int v = 0; v < 8; v++)
            g_proj[(v0 + v) * G4N + g] = acc[v] + bias;
    }
}

// ---------------------------------------------------------------------------
// Kernel 2: recurrence (R7 champion + vectorized exchange). 16 clusters x
// 8 CTAs; cluster owns 4 batch rows. Thread = (gate row lr, k-quarter q);
// W_hh k-quarter of one gate row in registers (32 u64). After the cell,
// lane 8j of each cell warp shfl-gathers 4 consecutive-h values and pushes
// ONE st.async.v4.b32 (16 B) per destination rank: 256 remote transactions
// per CTA per step instead of 1024 — 4x fewer fabric ops and mbarrier
// tx-updates at each destination, with zero added synchronization.
// ---------------------------------------------------------------------------
__global__ void __launch_bounds__(NTH, 1) __cluster_dims__(CL, 1, 1)
lstm_kernel(const int* __restrict__ tokens, const int* __restrict__ lengths,
            const float* __restrict__ W_hh, float* __restrict__ out)
{
    __shared__ float hb[2][GB][HIDN];          // 8 KB: double-buffered h, batch-major
    __shared__ float psum[4][GB][128];         // 8 KB: [quarter][batch][gate-row]
    __shared__ __align__(8) unsigned long long mbar[2];

    const int rank = blockIdx.x;               // 0..7
    const int cid  = blockIdx.y;               // 0..15
    const int tid  = threadIdx.x;
    const int lr   = tid & 127;                // gate row 0..127
    const int q    = tid >> 7;                 // k-quarter 0..3 (warp-uniform)
    const int base = rank * 32;
    const int b0   = cid * GB;
    const unsigned TXB = 4096;                 // bytes per exchange phase
    const int grow = (lr >> 5) * HIDN + base + (lr & 31);  // my W_hh row

    // --- W slice into registers: 64 floats (k-quarter of a row) = 32 pairs ---
    unsigned long long wpair[32];
    {
        const ulonglong2* wr =
            (const ulonglong2*)(W_hh + (size_t)grow * HIDN + q * 64);
#pragma unroll
        for (int j = 0; j < 16; j++) {
            ulonglong2 v = wr[j];
            wpair[2 * j]     = v.x;
            wpair[2 * j + 1] = v.y;
        }
    }

    const unsigned mb0 = smem_u32(&mbar[0]);
    const unsigned mb1 = smem_u32(&mbar[1]);
    if (tid == 0) {
        mbar_init(mb0, 1);
        mbar_init(mb1, 1);
        mbar_arm(mb1, TXB);    // pre-arm for t=1 data (arrives into hb[1])
    }
    for (int i = tid; i < GB * HIDN; i += NTH) ((float*)hb[0])[i] = 0.f;
    __syncthreads();
    cluster_sync_once();       // init + hb[0]=0 visible cluster-wide

    // cell identity (tid<256): lane pairs (2j,2j+1) share one (h,batch).
    // Within a cell warp, lane = 2*(pr&15) + s; hl spans a 16-range, bb fixed.
    const int pr = tid >> 1;        // 0..127 (for tid<256)
    const int s  = tid & 1;         // 0 -> {i,f}, 1 -> {g,o}
    const int hl = pr & 31;
    const int bb = pr >> 5;
    const int mylen = (tid < 256) ? lengths[b0 + bb] : 0;

    const int len0 = lengths[b0 + 0];
    const int len1 = lengths[b0 + 1];
    const int len2 = lengths[b0 + 2];
    const int len3 = lengths[b0 + 3];
    int steps = max(max(len0, len1), max(len2, len3));
    if (steps > TN) steps = TN;

    // input projections live in the q==0 threads (tid<128, one per gate row)
    float xw0 = 0.f, xw1 = 0.f, xw2 = 0.f, xw3 = 0.f;
    if (q == 0) {
        xw0 = g_proj[tokens[(b0 + 0) * TN] * G4N + grow];
        xw1 = g_proj[tokens[(b0 + 1) * TN] * G4N + grow];
        xw2 = g_proj[tokens[(b0 + 2) * TN] * G4N + grow];
        xw3 = g_proj[tokens[(b0 + 3) * TN] * G4N + grow];
    }

    float creg = 0.f, hreg = 0.f;
    unsigned ph0 = 0, ph1 = 0;
    const int lane = tid & 31;

    for (int t = 0; t < steps; t++) {
        const int buf = t & 1;
        // wait for h(t) (skip t=0: hb[0] prezeroed), then re-arm this barrier
        // for the phase two steps ahead.
        if (t) {
            if (buf) { mbar_wait(mb1, ph1); ph1 ^= 1; }
            else     { mbar_wait(mb0, ph0); ph0 ^= 1; }
        }
        if (tid == 0) mbar_arm(buf ? mb1 : mb0, TXB);

        // prefetch next step's input projection (L2 latency hidden by matvec)
        float xn0, xn1, xn2, xn3;
        if (q == 0) {
            int tn = min(t + 1, TN - 1);
            xn0 = g_proj[tokens[(b0 + 0) * TN + tn] * G4N + grow];
            xn1 = g_proj[tokens[(b0 + 1) * TN + tn] * G4N + grow];
            xn2 = g_proj[tokens[(b0 + 2) * TN + tn] * G4N + grow];
            xn3 = g_proj[tokens[(b0 + 3) * TN + tn] * G4N + grow];
        }

        // packed matvec: my gate row, my k-quarter, 4 batches.
        // W from registers; h via warp-uniform broadcast LDS.128.
        const float* h0p = hb[buf][0] + q * 64;
        const float* h1p = hb[buf][1] + q * 64;
        const float* h2p = hb[buf][2] + q * 64;
        const float* h3p = hb[buf][3] + q * 64;
        unsigned long long a0 = 0ull, a1 = 0ull, a2 = 0ull, a3 = 0ull;
#pragma unroll
        for (int c = 0; c < 16; c++) {
            ulonglong2 h0 = *(const ulonglong2*)(h0p + c * 4);
            ulonglong2 h1 = *(const ulonglong2*)(h1p + c * 4);
            ulonglong2 h2 = *(const ulonglong2*)(h2p + c * 4);
            ulonglong2 h3 = *(const ulonglong2*)(h3p + c * 4);
            a0 = fma2(wpair[2 * c], h0.x, a0);
            a1 = fma2(wpair[2 * c], h1.x, a1);
            a2 = fma2(wpair[2 * c], h2.x, a2);
            a3 = fma2(wpair[2 * c], h3.x, a3);
            a0 = fma2(wpair[2 * c + 1], h0.y, a0);
            a1 = fma2(wpair[2 * c + 1], h1.y, a1);
            a2 = fma2(wpair[2 * c + 1], h2.y, a2);
            a3 = fma2(wpair[2 * c + 1], h3.y, a3);
        }
        // pair-summed scalar partials; quarter 0 folds in the input projection
        if (q == 0) {
            psum[0][0][lr] = lo32(a0) + hi32(a0) + xw0;
            psum[0][1][lr] = lo32(a1) + hi32(a1) + xw1;
            psum[0][2][lr] = lo32(a2) + hi32(a2) + xw2;
            psum[0][3][lr] = lo32(a3) + hi32(a3) + xw3;
            xw0 = xn0; xw1 = xn1; xw2 = xn2; xw3 = xn3;
        } else {
            psum[q][0][lr] = lo32(a0) + hi32(a0);
            psum[q][1][lr] = lo32(a1) + hi32(a1);
            psum[q][2][lr] = lo32(a2) + hi32(a2);
            psum[q][3][lr] = lo32(a3) + hi32(a3);
        }
        __syncthreads();

        // cell update on tid<256; q=2,3 warps fall through to the next wait.
        if (tid < 256) {
            const int r0 = (s ? 64 : 0) + hl;
            const int r1 = (s ? 96 : 32) + hl;
            float gA = (psum[0][bb][r0] + psum[1][bb][r0]) +
                       (psum[2][bb][r0] + psum[3][bb][r0]);
            float gB = (psum[0][bb][r1] + psum[1][bb][r1]) +
                       (psum[2][bb][r1] + psum[3][bb][r1]);
            float u = s ? tanhf_(gA) : sigf(gA);
            float v = sigf(gB);
            float ou = __shfl_xor_sync(0xffffffffu, u, 1);
            float ov = __shfl_xor_sync(0xffffffffu, v, 1);
            float i_ = s ? ou : u;
            float f_ = s ? ov : v;
            float g_ = s ? u  : ou;
            float o_ = s ? v  : ov;
            float cn = f_ * creg + i_ * g_;
            float hn = o_ * tanhf_(cn);
            if (t < mylen) { creg = cn; hreg = hn; }

            if (t + 1 < steps) {
                // gather 4 consecutive-h values (even lanes hold them) into
                // lane 8j, then ONE 16-B st.async per destination rank.
                float v1 = __shfl_down_sync(0xffffffffu, hreg, 2);
                float v2 = __shfl_down_sync(0xffffffffu, hreg, 4);
                float v3 = __shfl_down_sync(0xffffffffu, hreg, 6);
                if ((lane & 7) == 0) {
                    const int nb = buf ^ 1;
                    const unsigned dloc = smem_u32(&hb[nb][bb][base + hl]);
                    const unsigned mloc = nb ? mb1 : mb0;
#pragma unroll
                    for (int r = 0; r < CL; r++) {
                        st_async_f32x4(mapa_u32(dloc, r), hreg, v1, v2, v3,
                                       mapa_u32(mloc, r));
                    }
                }
            }
        }
    }

    if (tid < 256 && s == 0)
        out[(b0 + bb) * HIDN + base + hl] = hreg;
}

// ---------------------------------------------------------------------------
extern "C" void kernel_launch(void* const* d_in, const int* in_sizes, int n_in,
                              void* d_out, int out_size)
{
    const int*   tokens  = (const int*)d_in[0];
    const int*   lengths = (const int*)d_in[1];
    const float* emb     = (const float*)d_in[2];
    const float* W_ih    = (const float*)d_in[3];
    const float* W_hh    = (const float*)d_in[4];
    const float* b_ih    = (const float*)d_in[5];
    const float* b_hh    = (const float*)d_in[6];
    float* out = (float*)d_out;

    proj_kernel<<<VOCABN / 8, 256>>>(emb, W_ih, b_ih, b_hh);

    dim3 grid(CL, BN / GB);
    lstm_kernel<<<grid, NTH>>>(tokens, lengths, W_hh, out);
}

// round 15
// speedup vs baseline: 3.3401x; 1.1078x over previous
#include <cuda_runtime.h>

#define VOCABN 1000
#define EMBN   128
#define HIDN   256
#define G4N    1024   // 4*HID
#define BN     64
#define TN     1024

#define CL     8      // CTAs per cluster
#define GB     4      // batch rows per cluster
#define NTH    512    // 64 row-pairs x 8 k-eighths

// Precomputed per-vocab gate projections: proj[v][g] = emb[v].W_ih[g] + b_ih[g] + b_hh[g]
__device__ float g_proj[VOCABN * G4N];

// ---------------- packed f32x2 helpers ----------------
__device__ __forceinline__ unsigned long long fma2(unsigned long long a,
                                                   unsigned long long b,
                                                   unsigned long long c) {
    unsigned long long d;
    asm("fma.rn.f32x2 %0, %1, %2, %3;" : "=l"(d) : "l"(a), "l"(b), "l"(c));
    return d;
}
__device__ __forceinline__ float lo32(unsigned long long v) {
    return __uint_as_float((unsigned)v);
}
__device__ __forceinline__ float hi32(unsigned long long v) {
    return __uint_as_float((unsigned)(v >> 32));
}

__device__ __forceinline__ float sigf(float x) {
    return __fdividef(1.0f, 1.0f + __expf(-x));
}
__device__ __forceinline__ float tanhf_(float x) {
    return 1.0f - __fdividef(2.0f, __expf(2.0f * x) + 1.0f);
}

// ---------------- cluster smem / mbarrier helpers ----------------
__device__ __forceinline__ unsigned smem_u32(const void* p) {
    return (unsigned)__cvta_generic_to_shared(p);
}
__device__ __forceinline__ void mbar_init(unsigned a, unsigned cnt) {
    asm volatile("mbarrier.init.shared.b64 [%0], %1;" :: "r"(a), "r"(cnt) : "memory");
}
__device__ __forceinline__ unsigned mapa_u32(unsigned a, unsigned rank) {
    unsigned r;
    asm("mapa.shared::cluster.u32 %0, %1, %2;" : "=r"(r) : "r"(a), "r"(rank));
    return r;
}
__device__ __forceinline__ void mbar_arm(unsigned a, unsigned tx_bytes) {
    asm volatile("mbarrier.arrive.expect_tx.shared.b64 _, [%0], %1;"
                 :: "r"(a), "r"(tx_bytes) : "memory");
}
// remote vector store (16 B), counts bytes into the destination's mbarrier
__device__ __forceinline__ void st_async_f32x4(unsigned dst, float v0, float v1,
                                               float v2, float v3, unsigned mb) {
    asm volatile(
        "st.async.shared::cluster.mbarrier::complete_tx::bytes.v4.b32 "
        "[%0], {%1, %2, %3, %4}, [%5];"
        :: "r"(dst), "r"(__float_as_uint(v0)), "r"(__float_as_uint(v1)),
           "r"(__float_as_uint(v2)), "r"(__float_as_uint(v3)), "r"(mb)
        : "memory");
}
__device__ __forceinline__ void mbar_wait(unsigned a, unsigned parity) {
    asm volatile(
        "{\n\t"
        ".reg .pred P;\n\t"
        "mbarrier.try_wait.parity.acquire.cluster.shared::cta.b64 P, [%0], %1;\n\t"
        "@P bra.uni WDONE_%=;\n\t"
        "WLOOP_%=:\n\t"
        "mbarrier.try_wait.parity.acquire.cluster.shared::cta.b64 P, [%0], %1, 0x989680;\n\t"
        "@!P bra.uni WLOOP_%=;\n\t"
        "WDONE_%=:\n\t"
        "}"
        :: "r"(a), "r"(parity) : "memory");
}
__device__ __forceinline__ void cluster_sync_once() {
    asm volatile("barrier.cluster.arrive.aligned;" ::: "memory");
    asm volatile("barrier.cluster.wait.aligned;" ::: "memory");
}

// ---------------------------------------------------------------------------
// Kernel 1: vocab projection table. 125 blocks x 256 threads, 8 vocab/block.
// ---------------------------------------------------------------------------
__global__ void __launch_bounds__(256) proj_kernel(
    const float* __restrict__ emb, const float* __restrict__ W_ih,
    const float* __restrict__ b_ih, const float* __restrict__ b_hh)
{
    __shared__ float4 es4[8][EMBN / 4];
    const int v0 = blockIdx.x * 8;
    const int tid = threadIdx.x;
    for (int i = tid; i < 8 * EMBN; i += 256) {
        int v = i >> 7, e = i & 127;
        ((float*)es4)[v * EMBN + e] = emb[(v0 + v) * EMBN + e];
    }
    __syncthreads();

    const float4* W4 = (const float4*)W_ih;
#pragma unroll
    for (int rr = 0; rr < 4; rr++) {
        int g = tid + rr * 256;
        float acc[8];
#pragma unroll
        for (int v = 0; v < 8; v++) acc[v] = 0.f;
        for (int e4 = 0; e4 < EMBN / 4; e4++) {
            float4 w = W4[g * (EMBN / 4) + e4];
#pragma unroll
            for (int v = 0; v < 8; v++) {
                float4 x = es4[v][e4];
                acc[v] += w.x * x.x + w.y * x.y + w.z * x.z + w.w * x.w;
            }
        }
        float bias = b_ih[g] + b_hh[g];
#pragma unroll
        for (int v = 0; v < 8; v++)
            g_proj[(v0 + v) * G4N + g] = acc[v] + bias;
    }
}

// ---------------------------------------------------------------------------
// Kernel 2: recurrence. 16 clusters x 8 CTAs; cluster owns 4 batch rows.
// Thread = (row-pair rp in 0..63, k-eighth q = tid>>6 — warp-uniform).
// Each thread computes gate rows rp AND rp+64 (same h index, gates g, g+2)
// over a 32-float k-chunk: 128 FFMA2 but only 32 LDS.128 per thread —
// each h load feeds 4 FMAs, halving the LDS-instruction pipe load that
// co-bound the step. W (2 rows x 32 k = 64 floats) in 32 u64 registers.
// psum float2-packed [q][batch][rp] = {row rp, row rp+64}. Exchange:
// R14's vectorized st.async.v4 + double-buffered tx mbarriers.
// ---------------------------------------------------------------------------
__global__ void __launch_bounds__(NTH, 1) __cluster_dims__(CL, 1, 1)
lstm_kernel(const int* __restrict__ tokens, const int* __restrict__ lengths,
            const float* __restrict__ W_hh, float* __restrict__ out)
{
    __shared__ float  hb[2][GB][HIDN];         // 8 KB: double-buffered h, batch-major
    __shared__ float2 psv[8][GB][64];          // 16 KB: [eighth][batch][row-pair]
    __shared__ __align__(8) unsigned long long mbar[2];

    const int rank = blockIdx.x;               // 0..7
    const int cid  = blockIdx.y;               // 0..15
    const int tid  = threadIdx.x;
    const int rp   = tid & 63;                 // row-pair 0..63
    const int q    = tid >> 6;                 // k-eighth 0..7 (warp-uniform)
    const int base = rank * 32;
    const int b0   = cid * GB;
    const unsigned TXB = 4096;                 // bytes per exchange phase
    const int hI   = rp & 31;
    const int gI   = rp >> 5;                  // gates gI and gI+2
    const int grow0 = gI * HIDN + base + hI;
    const int grow1 = grow0 + 2 * HIDN;

    // --- W slices into registers: 2 rows x 32 floats = 2 x 16 pairs ---
    unsigned long long w0[16], w1[16];
    {
        const ulonglong2* wr0 =
            (const ulonglong2*)(W_hh + (size_t)grow0 * HIDN + q * 32);
        const ulonglong2* wr1 =
            (const ulonglong2*)(W_hh + (size_t)grow1 * HIDN + q * 32);
#pragma unroll
        for (int j = 0; j < 8; j++) {
            ulonglong2 a = wr0[j];
            ulonglong2 b = wr1[j];
            w0[2 * j] = a.x; w0[2 * j + 1] = a.y;
            w1[2 * j] = b.x; w1[2 * j + 1] = b.y;
        }
    }

    const unsigned mb0 = smem_u32(&mbar[0]);
    const unsigned mb1 = smem_u32(&mbar[1]);
    if (tid == 0) {
        mbar_init(mb0, 1);
        mbar_init(mb1, 1);
        mbar_arm(mb1, TXB);    // pre-arm for t=1 data (arrives into hb[1])
    }
    for (int i = tid; i < GB * HIDN; i += NTH) ((float*)hb[0])[i] = 0.f;
    __syncthreads();
    cluster_sync_once();       // init + hb[0]=0 visible cluster-wide

    // cell identity (tid<256): lane pairs (2j,2j+1) share one (h,batch)
    const int pr = tid >> 1;        // 0..127 (for tid<256)
    const int s  = tid & 1;         // 0 -> {i,f}, 1 -> {g,o}
    const int hl = pr & 31;
    const int bb = pr >> 5;
    const int mylen = (tid < 256) ? lengths[b0 + bb] : 0;

    const int len0 = lengths[b0 + 0];
    const int len1 = lengths[b0 + 1];
    const int len2 = lengths[b0 + 2];
    const int len3 = lengths[b0 + 3];
    int steps = max(max(len0, len1), max(len2, len3));
    if (steps > TN) steps = TN;

    // input projections: q==0 threads (tid<64) hold both rows x 4 batches
    float xwA0 = 0.f, xwA1 = 0.f, xwA2 = 0.f, xwA3 = 0.f;
    float xwB0 = 0.f, xwB1 = 0.f, xwB2 = 0.f, xwB3 = 0.f;
    if (q == 0) {
        int t0 = tokens[(b0 + 0) * TN], t1 = tokens[(b0 + 1) * TN];
        int t2 = tokens[(b0 + 2) * TN], t3 = tokens[(b0 + 3) * TN];
        xwA0 = g_proj[t0 * G4N + grow0]; xwB0 = g_proj[t0 * G4N + grow1];
        xwA1 = g_proj[t1 * G4N + grow0]; xwB1 = g_proj[t1 * G4N + grow1];
        xwA2 = g_proj[t2 * G4N + grow0]; xwB2 = g_proj[t2 * G4N + grow1];
        xwA3 = g_proj[t3 * G4N + grow0]; xwB3 = g_proj[t3 * G4N + grow1];
    }

    float creg = 0.f, hreg = 0.f;
    unsigned ph0 = 0, ph1 = 0;
    const int lane = tid & 31;

    for (int t = 0; t < steps; t++) {
        const int buf = t & 1;
        // wait for h(t) (skip t=0: hb[0] prezeroed), then re-arm this barrier
        // for the phase two steps ahead.
        if (t) {
            if (buf) { mbar_wait(mb1, ph1); ph1 ^= 1; }
            else     { mbar_wait(mb0, ph0); ph0 ^= 1; }
        }
        if (tid == 0) mbar_arm(buf ? mb1 : mb0, TXB);

        // prefetch next step's input projections (hidden behind the matvec)
        float xnA0, xnA1, xnA2, xnA3, xnB0, xnB1, xnB2, xnB3;
        if (q == 0) {
            int tn = min(t + 1, TN - 1);
            int t0 = tokens[(b0 + 0) * TN + tn], t1 = tokens[(b0 + 1) * TN + tn];
            int t2 = tokens[(b0 + 2) * TN + tn], t3 = tokens[(b0 + 3) * TN + tn];
            xnA0 = g_proj[t0 * G4N + grow0]; xnB0 = g_proj[t0 * G4N + grow1];
            xnA1 = g_proj[t1 * G4N + grow0]; xnB1 = g_proj[t1 * G4N + grow1];
            xnA2 = g_proj[t2 * G4N + grow0]; xnB2 = g_proj[t2 * G4N + grow1];
            xnA3 = g_proj[t3 * G4N + grow0]; xnB3 = g_proj[t3 * G4N + grow1];
        }

        // packed matvec: 2 gate rows, my k-eighth, 4 batches.
        // 32 LDS.128 + 128 FFMA2: each h load feeds 4 FMAs.
        const float* h0p = hb[buf][0] + q * 32;
        const float* h1p = hb[buf][1] + q * 32;
        const float* h2p = hb[buf][2] + q * 32;
        const float* h3p = hb[buf][3] + q * 32;
        unsigned long long aA0 = 0ull, aA1 = 0ull, aA2 = 0ull, aA3 = 0ull;
        unsigned long long aB0 = 0ull, aB1 = 0ull, aB2 = 0ull, aB3 = 0ull;
#pragma unroll
        for (int c = 0; c < 8; c++) {
            ulonglong2 h0 = *(const ulonglong2*)(h0p + c * 4);
            ulonglong2 h1 = *(const ulonglong2*)(h1p + c * 4);
            ulonglong2 h2 = *(const ulonglong2*)(h2p + c * 4);
            ulonglong2 h3 = *(const ulonglong2*)(h3p + c * 4);
            aA0 = fma2(w0[2 * c], h0.x, aA0);
            aA1 = fma2(w0[2 * c], h1.x, aA1);
            aA2 = fma2(w0[2 * c], h2.x, aA2);
            aA3 = fma2(w0[2 * c], h3.x, aA3);
            aB0 = fma2(w1[2 * c], h0.x, aB0);
            aB1 = fma2(w1[2 * c], h1.x, aB1);
            aB2 = fma2(w1[2 * c], h2.x, aB2);
            aB3 = fma2(w1[2 * c], h3.x, aB3);
            aA0 = fma2(w0[2 * c + 1], h0.y, aA0);
            aA1 = fma2(w0[2 * c + 1], h1.y, aA1);
            aA2 = fma2(w0[2 * c + 1], h2.y, aA2);
            aA3 = fma2(w0[2 * c + 1], h3.y, aA3);
            aB0 = fma2(w1[2 * c + 1], h0.y, aB0);
            aB1 = fma2(w1[2 * c + 1], h1.y, aB1);
            aB2 = fma2(w1[2 * c + 1], h2.y, aB2);
            aB3 = fma2(w1[2 * c + 1], h3.y, aB3);
        }
        // pair-summed partials, float2-packed {row rp, row rp+64}
        if (q == 0) {
            psv[0][0][rp] = make_float2(lo32(aA0) + hi32(aA0) + xwA0,
                                        lo32(aB0) + hi32(aB0) + xwB0);
            psv[0][1][rp] = make_float2(lo32(aA1) + hi32(aA1) + xwA1,
                                        lo32(aB1) + hi32(aB1) + xwB1);
            psv[0][2][rp] = make_float2(lo32(aA2) + hi32(aA2) + xwA2,
                                        lo32(aB2) + hi32(aB2) + xwB2);
            psv[0][3][rp] = make_float2(lo32(aA3) + hi32(aA3) + xwA3,
                                        lo32(aB3) + hi32(aB3) + xwB3);
            xwA0 = xnA0; xwA1 = xnA1; xwA2 = xnA2; xwA3 = xnA3;
            xwB0 = xnB0; xwB1 = xnB1; xwB2 = xnB2; xwB3 = xnB3;
        } else {
            psv[q][0][rp] = make_float2(lo32(aA0) + hi32(aA0),
                                        lo32(aB0) + hi32(aB0));
            psv[q][1][rp] = make_float2(lo32(aA1) + hi32(aA1),
                                        lo32(aB1) + hi32(aB1));
            psv[q][2][rp] = make_float2(lo32(aA2) + hi32(aA2),
                                        lo32(aB2) + hi32(aB2));
            psv[q][3][rp] = make_float2(lo32(aA3) + hi32(aA3),
                                        lo32(aB3) + hi32(aB3));
        }
        __syncthreads();

        // cell update on tid<256.
        // s=0 gates {i,f} = rows hl, 32+hl   -> .x of pairs hl, 32+hl
        // s=1 gates {g,o} = rows 64+hl,96+hl -> .y of pairs hl, 32+hl
        if (tid < 256) {
            float gA, gB;
            if (s == 0) {
                gA = ((psv[0][bb][hl].x + psv[1][bb][hl].x) +
                      (psv[2][bb][hl].x + psv[3][bb][hl].x)) +
                     ((psv[4][bb][hl].x + psv[5][bb][hl].x) +
                      (psv[6][bb][hl].x + psv[7][bb][hl].x));
                gB = ((psv[0][bb][32 + hl].x + psv[1][bb][32 + hl].x) +
                      (psv[2][bb][32 + hl].x + psv[3][bb][32 + hl].x)) +
                     ((psv[4][bb][32 + hl].x + psv[5][bb][32 + hl].x) +
                      (psv[6][bb][32 + hl].x + psv[7][bb][32 + hl].x));
            } else {
                gA = ((psv[0][bb][hl].y + psv[1][bb][hl].y) +
                      (psv[2][bb][hl].y + psv[3][bb][hl].y)) +
                     ((psv[4][bb][hl].y + psv[5][bb][hl].y) +
                      (psv[6][bb][hl].y + psv[7][bb][hl].y));
                gB = ((psv[0][bb][32 + hl].y + psv[1][bb][32 + hl].y) +
                      (psv[2][bb][32 + hl].y + psv[3][bb][32 + hl].y)) +
                     ((psv[4][bb][32 + hl].y + psv[5][bb][32 + hl].y) +
                      (psv[6][bb][32 + hl].y + psv[7][bb][32 + hl].y));
            }
            float u = s ? tanhf_(gA) : sigf(gA);
            float v = sigf(gB);
            float ou = __shfl_xor_sync(0xffffffffu, u, 1);
            float ov = __shfl_xor_sync(0xffffffffu, v, 1);
            float i_ = s ? ou : u;
            float f_ = s ? ov : v;
            float g_ = s ? u  : ou;
            float o_ = s ? v  : ov;
            float cn = f_ * creg + i_ * g_;
            float hn = o_ * tanhf_(cn);
            if (t < mylen) { creg = cn; hreg = hn; }

            if (t + 1 < steps) {
                // gather 4 consecutive-h values into lane 8j, one 16-B
                // st.async per destination rank (R14 exchange).
                float v1 = __shfl_down_sync(0xffffffffu, hreg, 2);
                float v2 = __shfl_down_sync(0xffffffffu, hreg, 4);
                float v3 = __shfl_down_sync(0xffffffffu, hreg, 6);
                if ((lane & 7) == 0) {
                    const int nb = buf ^ 1;
                    const unsigned dloc = smem_u32(&hb[nb][bb][base + hl]);
                    const unsigned mloc = nb ? mb1 : mb0;
#pragma unroll
                    for (int r = 0; r < CL; r++) {
                        st_async_f32x4(mapa_u32(dloc, r), hreg, v1, v2, v3,
                                       mapa_u32(mloc, r));
                    }
                }
            }
        }
    }

    if (tid < 256 && s == 0)
        out[(b0 + bb) * HIDN + base + hl] = hreg;
}

// ---------------------------------------------------------------------------
extern "C" void kernel_launch(void* const* d_in, const int* in_sizes, int n_in,
                              void* d_out, int out_size)
{
    const int*   tokens  = (const int*)d_in[0];
    const int*   lengths = (const int*)d_in[1];
    const float* emb     = (const float*)d_in[2];
    const float* W_ih    = (const float*)d_in[3];
    const float* W_hh    = (const float*)d_in[4];
    const float* b_ih    = (const float*)d_in[5];
    const float* b_hh    = (const float*)d_in[6];
    float* out = (float*)d_out;

    proj_kernel<<<VOCABN / 8, 256>>>(emb, W_ih, b_ih, b_hh);

    dim3 grid(CL, BN / GB);
    lstm_kernel<<<grid, NTH>>>(tokens, lengths, W_hh, out);
}